// round 2
// baseline (speedup 1.0000x reference)
#include <cuda_runtime.h>
#include <cuda_bf16.h>
#include <math_constants.h>

// Problem constants
#define BATCH 16
#define SEQ   4096
#define EMB   2048
#define WIN   64

// Scratch for per-token scores (static device array: allocation-free)
__device__ float g_scores[BATCH * SEQ];

// ---------------------------------------------------------------------------
// Kernel 1: s[b,t] = mask[b,t] ? dot(x[b,t,:], W) + bias : 0
// One warp per row. float4 loads, W in shared.
// ---------------------------------------------------------------------------
__global__ __launch_bounds__(256) void score_kernel(
    const float* __restrict__ x,
    const int*   __restrict__ mask,   // bool mask coerced to int32 by harness
    const float* __restrict__ W,
    const float* __restrict__ bias)
{
    __shared__ float sW[EMB];
    for (int i = threadIdx.x; i < EMB; i += blockDim.x)
        sW[i] = W[i];
    __syncthreads();

    const int warpsPerBlock = blockDim.x >> 5;
    const int warp = blockIdx.x * warpsPerBlock + (threadIdx.x >> 5);
    const int lane = threadIdx.x & 31;
    if (warp >= BATCH * SEQ) return;

    const float4* __restrict__ xr = reinterpret_cast<const float4*>(x + (size_t)warp * EMB);
    const float4* __restrict__ wr = reinterpret_cast<const float4*>(sW);

    float acc = 0.0f;
    // EMB/4 = 512 float4 per row; 32 lanes -> 16 iters
    #pragma unroll
    for (int i = 0; i < EMB / (4 * 32); i++) {
        float4 a = xr[lane + i * 32];
        float4 w = wr[lane + i * 32];
        acc = fmaf(a.x, w.x, acc);
        acc = fmaf(a.y, w.y, acc);
        acc = fmaf(a.z, w.z, acc);
        acc = fmaf(a.w, w.w, acc);
    }

    // warp reduce
    #pragma unroll
    for (int o = 16; o > 0; o >>= 1)
        acc += __shfl_xor_sync(0xffffffffu, acc, o);

    if (lane == 0) {
        float v = (mask[warp] != 0) ? (acc + bias[0]) : 0.0f;
        g_scores[warp] = v;
    }
}

// ---------------------------------------------------------------------------
// Kernel 2: per batch, sliding-window(64) sums over S=4096 scores, take max,
// divide by WIN at the end. One block per batch.
// ---------------------------------------------------------------------------
__global__ __launch_bounds__(256) void window_max_kernel(float* __restrict__ out)
{
    __shared__ float s[SEQ];
    __shared__ float red[256];

    const int b = blockIdx.x;
    for (int i = threadIdx.x; i < SEQ; i += blockDim.x)
        s[i] = g_scores[b * SEQ + i];
    __syncthreads();

    float best = -CUDART_INF_F;
    // windows 0 .. SEQ-WIN (inclusive): 4033 windows
    for (int i = threadIdx.x; i <= SEQ - WIN; i += blockDim.x) {
        float sum = 0.0f;
        #pragma unroll
        for (int k = 0; k < WIN; k++)
            sum += s[i + k];
        best = fmaxf(best, sum);
    }

    red[threadIdx.x] = best;
    __syncthreads();
    for (int stride = 128; stride > 0; stride >>= 1) {
        if (threadIdx.x < stride)
            red[threadIdx.x] = fmaxf(red[threadIdx.x], red[threadIdx.x + stride]);
        __syncthreads();
    }

    if (threadIdx.x == 0)
        out[b] = red[0] * (1.0f / (float)WIN);
}

// ---------------------------------------------------------------------------
// Launch
// ---------------------------------------------------------------------------
extern "C" void kernel_launch(void* const* d_in, const int* in_sizes, int n_in,
                              void* d_out, int out_size)
{
    const float* x    = (const float*)d_in[0];
    const int*   mask = (const int*)d_in[1];
    const float* W    = (const float*)d_in[2];
    const float* bias = (const float*)d_in[3];
    float*       out  = (float*)d_out;

    // Kernel 1: one warp per row, 8 warps per 256-thread block
    const int totalRows = BATCH * SEQ;               // 65536
    const int warpsPerBlock = 256 / 32;              // 8
    const int grid1 = (totalRows + warpsPerBlock - 1) / warpsPerBlock; // 8192
    score_kernel<<<grid1, 256>>>(x, mask, W, bias);

    // Kernel 2: one block per batch
    window_max_kernel<<<BATCH, 256>>>(out);
}

// round 3
// speedup vs baseline: 1.0675x; 1.0675x over previous
#include <cuda_runtime.h>
#include <cuda_bf16.h>
#include <math_constants.h>

// Problem constants
#define BATCH 16
#define SEQ   4096
#define EMB   2048
#define WIN   64

// Scratch for per-token scores (static device array: allocation-free)
__device__ float g_scores[BATCH * SEQ];

// ---------------------------------------------------------------------------
// Kernel 1: s[b,t] = mask[b,t] ? dot(x[b,t,:], W) + bias : 0
// One warp per row. float4 loads batched 8-deep for MLP, W in shared.
// ---------------------------------------------------------------------------
__global__ __launch_bounds__(256) void score_kernel(
    const float* __restrict__ x,
    const int*   __restrict__ mask,   // bool mask coerced to int32 by harness
    const float* __restrict__ W,
    const float* __restrict__ bias)
{
    __shared__ float sW[EMB];
    for (int i = threadIdx.x; i < EMB; i += blockDim.x)
        sW[i] = W[i];
    __syncthreads();

    const int warpsPerBlock = blockDim.x >> 5;
    const int warp = blockIdx.x * warpsPerBlock + (threadIdx.x >> 5);
    const int lane = threadIdx.x & 31;
    if (warp >= BATCH * SEQ) return;

    const float4* __restrict__ xr = reinterpret_cast<const float4*>(x + (size_t)warp * EMB);
    const float4* __restrict__ wr = reinterpret_cast<const float4*>(sW);

    float acc = 0.0f;
    // EMB/4 = 512 float4 per row; 32 lanes -> 16 float4 per lane.
    // Two half-passes of 8 front-batched independent LDG.128 each (MLP=8).
    #pragma unroll
    for (int h = 0; h < 2; h++) {
        float4 a[8];
        #pragma unroll
        for (int j = 0; j < 8; j++)
            a[j] = xr[lane + (h * 8 + j) * 32];
        #pragma unroll
        for (int j = 0; j < 8; j++) {
            float4 w = wr[lane + (h * 8 + j) * 32];
            acc = fmaf(a[j].x, w.x, acc);
            acc = fmaf(a[j].y, w.y, acc);
            acc = fmaf(a[j].z, w.z, acc);
            acc = fmaf(a[j].w, w.w, acc);
        }
    }

    // warp reduce
    #pragma unroll
    for (int o = 16; o > 0; o >>= 1)
        acc += __shfl_xor_sync(0xffffffffu, acc, o);

    if (lane == 0) {
        float v = (mask[warp] != 0) ? (acc + bias[0]) : 0.0f;
        g_scores[warp] = v;
    }
}

// ---------------------------------------------------------------------------
// Kernel 2: per batch, sliding-window(64) sums over S=4096 scores, take max,
// divide by WIN at the end. One block (1024 threads) per batch.
// Each thread handles 4 consecutive windows with a rolling sum.
// ---------------------------------------------------------------------------
__global__ __launch_bounds__(1024) void window_max_kernel(float* __restrict__ out)
{
    __shared__ float s[SEQ];
    __shared__ float red[32];

    const int b   = blockIdx.x;
    const int tid = threadIdx.x;

    // coalesced load of this batch's scores (float4)
    {
        const float4* src = reinterpret_cast<const float4*>(g_scores + b * SEQ);
        float4*       dst = reinterpret_cast<float4*>(s);
        if (tid < SEQ / 4) dst[tid] = src[tid];
    }
    __syncthreads();

    // windows 0 .. SEQ-WIN (4033 windows). Thread t covers starts 4t..4t+3.
    const int start = tid * 4;
    float best = -CUDART_INF_F;
    if (start <= SEQ - WIN) {
        float sum = 0.0f;
        #pragma unroll
        for (int k = 0; k < WIN; k++)
            sum += s[start + k];
        best = sum;
        #pragma unroll
        for (int j = 1; j < 4; j++) {
            int i = start + j;
            if (i <= SEQ - WIN) {
                sum += s[i + WIN - 1] - s[i - 1];
                best = fmaxf(best, sum);
            }
        }
    }

    // block max reduce: warp shuffle, then cross-warp via smem
    #pragma unroll
    for (int o = 16; o > 0; o >>= 1)
        best = fmaxf(best, __shfl_xor_sync(0xffffffffu, best, o));
    if ((tid & 31) == 0) red[tid >> 5] = best;
    __syncthreads();
    if (tid < 32) {
        float v = red[tid];  // blockDim=1024 -> exactly 32 warps
        #pragma unroll
        for (int o = 16; o > 0; o >>= 1)
            v = fmaxf(v, __shfl_xor_sync(0xffffffffu, v, o));
        if (tid == 0)
            out[b] = v * (1.0f / (float)WIN);
    }
}

// ---------------------------------------------------------------------------
// Launch
// ---------------------------------------------------------------------------
extern "C" void kernel_launch(void* const* d_in, const int* in_sizes, int n_in,
                              void* d_out, int out_size)
{
    const float* x    = (const float*)d_in[0];
    const int*   mask = (const int*)d_in[1];
    const float* W    = (const float*)d_in[2];
    const float* bias = (const float*)d_in[3];
    float*       out  = (float*)d_out;

    // Kernel 1: one warp per row, 8 warps per 256-thread block
    const int totalRows = BATCH * SEQ;               // 65536
    const int warpsPerBlock = 256 / 32;              // 8
    const int grid1 = (totalRows + warpsPerBlock - 1) / warpsPerBlock; // 8192
    score_kernel<<<grid1, 256>>>(x, mask, W, bias);

    // Kernel 2: one block per batch
    window_max_kernel<<<BATCH, 1024>>>(out);
}